// round 1
// baseline (speedup 1.0000x reference)
#include <cuda_runtime.h>

#define NN   100000
#define EE   640000
#define INCH 256
#define HIDC 128
#define OUTC 64

// ---------------- scratch (device globals; no allocation allowed) ----------------
__device__ float g_hpre[(size_t)NN * HIDC];   // x @ W1
__device__ float g_h[(size_t)NN * HIDC];      // relu(agg1)
__device__ float g_g[(size_t)NN * HIDC];      // h @ [W_mu | W_ls]
__device__ float g_dinv[NN];
__device__ int   g_deg[NN];
__device__ int   g_rowptr[NN + 1];
__device__ int   g_cursor[NN];
__device__ int   g_csrc[EE];
__device__ int   g_bsum[128];

// ---------------- graph setup ----------------
__global__ void k_init_deg() {
    int i = blockIdx.x * blockDim.x + threadIdx.x;
    if (i < NN) g_deg[i] = 1;  // self loop
}

__global__ void k_count(const int* __restrict__ ei) {
    int e = blockIdx.x * blockDim.x + threadIdx.x;
    if (e < EE) atomicAdd(&g_deg[ei[EE + e]], 1);
}

__global__ void k_dinv() {
    int i = blockIdx.x * blockDim.x + threadIdx.x;
    if (i < NN) g_dinv[i] = rsqrtf((float)g_deg[i]);
}

// exclusive scan of (deg-1) -> rowptr, 3-phase
__global__ void k_scan1() {
    __shared__ int s[1024];
    int i = blockIdx.x * 1024 + threadIdx.x;
    int v = (i < NN) ? (g_deg[i] - 1) : 0;
    s[threadIdx.x] = v;
    __syncthreads();
#pragma unroll
    for (int off = 1; off < 1024; off <<= 1) {
        int t = (threadIdx.x >= off) ? s[threadIdx.x - off] : 0;
        __syncthreads();
        s[threadIdx.x] += t;
        __syncthreads();
    }
    if (i < NN) g_rowptr[i] = s[threadIdx.x] - v;  // exclusive within block
    if (threadIdx.x == 1023) g_bsum[blockIdx.x] = s[1023];
}

__global__ void k_scan2() {  // 1 block, 128 threads
    __shared__ int s[128];
    int nblk = (NN + 1023) / 1024;
    int v = (threadIdx.x < nblk) ? g_bsum[threadIdx.x] : 0;
    s[threadIdx.x] = v;
    __syncthreads();
#pragma unroll
    for (int off = 1; off < 128; off <<= 1) {
        int t = (threadIdx.x >= off) ? s[threadIdx.x - off] : 0;
        __syncthreads();
        s[threadIdx.x] += t;
        __syncthreads();
    }
    g_bsum[threadIdx.x] = s[threadIdx.x] - v;  // exclusive block offsets
}

__global__ void k_scan3() {
    int i = blockIdx.x * 1024 + threadIdx.x;
    if (i < NN) {
        int rp = g_rowptr[i] + g_bsum[blockIdx.x];
        g_rowptr[i] = rp;
        g_cursor[i] = rp;
    }
    if (i == 0) g_rowptr[NN] = EE;
}

__global__ void k_fill(const int* __restrict__ ei) {
    int e = blockIdx.x * blockDim.x + threadIdx.x;
    if (e < EE) {
        int src = ei[e];
        int dst = ei[EE + e];
        int p = atomicAdd(&g_cursor[dst], 1);
        g_csrc[p] = src;
    }
}

// ---------------- SGEMM: C[M,128] = A[M,K] @ B[K,128] ----------------
// B is given as two halves (cols 0..63 from Bm, 64..127 from Bl), row stride strideB.
__global__ void __launch_bounds__(256) k_gemm(
    const float* __restrict__ A,
    const float* __restrict__ Bm, const float* __restrict__ Bl, int strideB,
    int K, int M, float* __restrict__ C)
{
    const int BM = 64, BK = 16;
    __shared__ float As[BK][68];      // k-major, padded
    __shared__ float Bs[BK][HIDC];

    int tid = threadIdx.x;
    int row0 = blockIdx.x * BM;
    int tx = tid & 31;   // col group: cols tx*4..tx*4+3
    int ty = tid >> 5;   // row group: rows ty*8..ty*8+7

    float acc[8][4];
#pragma unroll
    for (int r = 0; r < 8; r++)
#pragma unroll
        for (int c = 0; c < 4; c++) acc[r][c] = 0.f;

    int ar = tid >> 2;         // 0..63 : A row within tile
    int ak = (tid & 3) * 4;    // 0,4,8,12 : k offset

    for (int k0 = 0; k0 < K; k0 += BK) {
        // load A tile (64x16), transpose into k-major smem
        float4 av = make_float4(0.f, 0.f, 0.f, 0.f);
        int arow = row0 + ar;
        if (arow < M) av = *(const float4*)(A + (size_t)arow * K + k0 + ak);
        As[ak + 0][ar] = av.x;
        As[ak + 1][ar] = av.y;
        As[ak + 2][ar] = av.z;
        As[ak + 3][ar] = av.w;
        // load B tile (16x128): 2 float4 per thread
#pragma unroll
        for (int t = 0; t < 2; t++) {
            int idx = tid + t * 256;       // 0..511
            int kr = idx >> 5;             // 0..15
            int nc = (idx & 31) * 4;       // 0..124
            const float* src = (nc < 64)
                ? (Bm + (size_t)(k0 + kr) * strideB + nc)
                : (Bl + (size_t)(k0 + kr) * strideB + nc - 64);
            *(float4*)&Bs[kr][nc] = *(const float4*)src;
        }
        __syncthreads();
#pragma unroll
        for (int kk = 0; kk < BK; kk++) {
            float4 a0 = *(const float4*)&As[kk][ty * 8];
            float4 a1 = *(const float4*)&As[kk][ty * 8 + 4];
            float4 b  = *(const float4*)&Bs[kk][tx * 4];
            float arr[8] = {a0.x, a0.y, a0.z, a0.w, a1.x, a1.y, a1.z, a1.w};
            float bc[4]  = {b.x, b.y, b.z, b.w};
#pragma unroll
            for (int r = 0; r < 8; r++)
#pragma unroll
                for (int c = 0; c < 4; c++)
                    acc[r][c] = fmaf(arr[r], bc[c], acc[r][c]);
        }
        __syncthreads();
    }
#pragma unroll
    for (int r = 0; r < 8; r++) {
        int row = row0 + ty * 8 + r;
        if (row < M) {
            float4 o = make_float4(acc[r][0], acc[r][1], acc[r][2], acc[r][3]);
            *(float4*)&C[(size_t)row * HIDC + tx * 4] = o;
        }
    }
}

// ---------------- aggregation: warp per node, float4 per lane ----------------
__global__ void __launch_bounds__(256) k_agg1(const float* __restrict__ b1) {
    int warp = (blockIdx.x * blockDim.x + threadIdx.x) >> 5;
    int lane = threadIdx.x & 31;
    if (warp >= NN) return;
    int v = warp;
    float dv = g_dinv[v];
    const float4* H = (const float4*)g_hpre;
    float4 self = H[(size_t)v * 32 + lane];
    float4 acc;
    acc.x = self.x * dv; acc.y = self.y * dv; acc.z = self.z * dv; acc.w = self.w * dv;
    int e1 = g_rowptr[v + 1];
    for (int e = g_rowptr[v]; e < e1; e++) {
        int s = g_csrc[e];
        float w = g_dinv[s];
        float4 hv = H[(size_t)s * 32 + lane];
        acc.x = fmaf(w, hv.x, acc.x);
        acc.y = fmaf(w, hv.y, acc.y);
        acc.z = fmaf(w, hv.z, acc.z);
        acc.w = fmaf(w, hv.w, acc.w);
    }
    float4 bb = ((const float4*)b1)[lane];
    float4 o;
    o.x = fmaxf(fmaf(acc.x, dv, bb.x), 0.f);
    o.y = fmaxf(fmaf(acc.y, dv, bb.y), 0.f);
    o.z = fmaxf(fmaf(acc.z, dv, bb.z), 0.f);
    o.w = fmaxf(fmaf(acc.w, dv, bb.w), 0.f);
    ((float4*)g_h)[(size_t)v * 32 + lane] = o;
}

__global__ void __launch_bounds__(256) k_agg2(
    const float* __restrict__ bmu, const float* __restrict__ bls,
    float* __restrict__ out)
{
    int warp = (blockIdx.x * blockDim.x + threadIdx.x) >> 5;
    int lane = threadIdx.x & 31;
    if (warp >= NN) return;
    int v = warp;
    float dv = g_dinv[v];
    const float4* G = (const float4*)g_g;
    float4 self = G[(size_t)v * 32 + lane];
    float4 acc;
    acc.x = self.x * dv; acc.y = self.y * dv; acc.z = self.z * dv; acc.w = self.w * dv;
    int e1 = g_rowptr[v + 1];
    for (int e = g_rowptr[v]; e < e1; e++) {
        int s = g_csrc[e];
        float w = g_dinv[s];
        float4 hv = G[(size_t)s * 32 + lane];
        acc.x = fmaf(w, hv.x, acc.x);
        acc.y = fmaf(w, hv.y, acc.y);
        acc.z = fmaf(w, hv.z, acc.z);
        acc.w = fmaf(w, hv.w, acc.w);
    }
    if (lane < 16) {  // channels lane*4 .. lane*4+3  (< 64): mu
        float4 bb = ((const float4*)bmu)[lane];
        float4 o;
        o.x = fmaf(acc.x, dv, bb.x);
        o.y = fmaf(acc.y, dv, bb.y);
        o.z = fmaf(acc.z, dv, bb.z);
        o.w = fmaf(acc.w, dv, bb.w);
        ((float4*)out)[(size_t)v * 16 + lane] = o;
    } else {          // channels >= 64: logstd
        float4 bb = ((const float4*)bls)[lane - 16];
        float4 o;
        o.x = fmaf(acc.x, dv, bb.x);
        o.y = fmaf(acc.y, dv, bb.y);
        o.z = fmaf(acc.z, dv, bb.z);
        o.w = fmaf(acc.w, dv, bb.w);
        ((float4*)(out + (size_t)NN * OUTC))[(size_t)v * 16 + (lane - 16)] = o;
    }
}

// ---------------- launch ----------------
extern "C" void kernel_launch(void* const* d_in, const int* in_sizes, int n_in,
                              void* d_out, int out_size) {
    const float* x    = (const float*)d_in[0];
    const float* W1   = (const float*)d_in[1];
    const float* b1   = (const float*)d_in[2];
    const float* Wmu  = (const float*)d_in[3];
    const float* bmu  = (const float*)d_in[4];
    const float* Wls  = (const float*)d_in[5];
    const float* bls  = (const float*)d_in[6];
    const int*   ei   = (const int*)d_in[7];
    float* out = (float*)d_out;

    void *p_hpre = nullptr, *p_h = nullptr, *p_g = nullptr;
    cudaGetSymbolAddress(&p_hpre, g_hpre);
    cudaGetSymbolAddress(&p_h, g_h);
    cudaGetSymbolAddress(&p_g, g_g);

    int nblk_n = (NN + 255) / 256;
    int nblk_e = (EE + 255) / 256;
    int nblk_s = (NN + 1023) / 1024;   // 98

    k_init_deg<<<nblk_n, 256>>>();
    k_count<<<nblk_e, 256>>>(ei);
    k_dinv<<<nblk_n, 256>>>();
    k_scan1<<<nblk_s, 1024>>>();
    k_scan2<<<1, 128>>>();
    k_scan3<<<nblk_s, 1024>>>();
    k_fill<<<nblk_e, 256>>>(ei);

    int gblk = (NN + 63) / 64;  // 1563
    // layer 1: hpre = x @ W1
    k_gemm<<<gblk, 256>>>(x, W1, W1 + 64, HIDC, INCH, NN, (float*)p_hpre);
    k_agg1<<<(NN * 32 + 255) / 256, 256>>>(b1);
    // layer 2: g = h @ [W_mu | W_ls]
    k_gemm<<<gblk, 256>>>((const float*)p_h, Wmu, Wls, OUTC, HIDC, NN, (float*)p_g);
    k_agg2<<<(NN * 32 + 255) / 256, 256>>>(bmu, bls, out);
}

// round 5
// speedup vs baseline: 1.6137x; 1.6137x over previous
#include <cuda_runtime.h>
#include <cuda_bf16.h>
#include <cstdint>

#define NN   100000
#define EE   640000
#define INCH 256
#define HIDC 128
#define OUTC 64

// ---------------- scratch (device globals; no allocation allowed) ----------------
__device__ float g_hpre[(size_t)NN * HIDC];   // x @ W1
__device__ float g_h[(size_t)NN * HIDC];      // relu(agg1)
__device__ float g_g[(size_t)NN * HIDC];      // h @ [W_mu | W_ls]
__device__ float g_dinv[NN];
__device__ int   g_deg[NN];
__device__ int   g_rowptr[NN + 1];
__device__ int   g_cursor[NN];
__device__ int   g_csrc[EE];
__device__ int   g_bsum[128];
// transposed, hi/lo-split bf16 weights: Bt[n][k]
__device__ __nv_bfloat16 g_bt1h[128 * INCH];
__device__ __nv_bfloat16 g_bt1l[128 * INCH];
__device__ __nv_bfloat16 g_bt2h[128 * HIDC];
__device__ __nv_bfloat16 g_bt2l[128 * HIDC];

__device__ __forceinline__ uint32_t smem_u32(const void* p) {
    uint32_t a;
    asm("{ .reg .u64 t; cvta.to.shared.u64 t, %1; cvt.u32.u64 %0, t; }" : "=r"(a) : "l"(p));
    return a;
}

// ---------------- graph setup ----------------
__global__ void k_init_deg() {
    int i = blockIdx.x * blockDim.x + threadIdx.x;
    if (i < NN) g_deg[i] = 1;
}
__global__ void k_count(const int* __restrict__ ei) {
    int e = blockIdx.x * blockDim.x + threadIdx.x;
    if (e < EE) atomicAdd(&g_deg[ei[EE + e]], 1);
}
__global__ void k_dinv() {
    int i = blockIdx.x * blockDim.x + threadIdx.x;
    if (i < NN) g_dinv[i] = rsqrtf((float)g_deg[i]);
}
__global__ void k_scan1() {
    __shared__ int s[1024];
    int i = blockIdx.x * 1024 + threadIdx.x;
    int v = (i < NN) ? (g_deg[i] - 1) : 0;
    s[threadIdx.x] = v;
    __syncthreads();
#pragma unroll
    for (int off = 1; off < 1024; off <<= 1) {
        int t = (threadIdx.x >= off) ? s[threadIdx.x - off] : 0;
        __syncthreads();
        s[threadIdx.x] += t;
        __syncthreads();
    }
    if (i < NN) g_rowptr[i] = s[threadIdx.x] - v;
    if (threadIdx.x == 1023) g_bsum[blockIdx.x] = s[1023];
}
__global__ void k_scan2() {
    __shared__ int s[128];
    int nblk = (NN + 1023) / 1024;
    int v = (threadIdx.x < nblk) ? g_bsum[threadIdx.x] : 0;
    s[threadIdx.x] = v;
    __syncthreads();
#pragma unroll
    for (int off = 1; off < 128; off <<= 1) {
        int t = (threadIdx.x >= off) ? s[threadIdx.x - off] : 0;
        __syncthreads();
        s[threadIdx.x] += t;
        __syncthreads();
    }
    g_bsum[threadIdx.x] = s[threadIdx.x] - v;
}
__global__ void k_scan3() {
    int i = blockIdx.x * 1024 + threadIdx.x;
    if (i < NN) {
        int rp = g_rowptr[i] + g_bsum[blockIdx.x];
        g_rowptr[i] = rp;
        g_cursor[i] = rp;
    }
    if (i == 0) g_rowptr[NN] = EE;
}
__global__ void k_fill(const int* __restrict__ ei) {
    int e = blockIdx.x * blockDim.x + threadIdx.x;
    if (e < EE) {
        int p = atomicAdd(&g_cursor[ei[EE + e]], 1);
        g_csrc[p] = ei[e];
    }
}

// ---------------- weight prep: transpose + hi/lo bf16 split ----------------
__global__ void k_prepB1(const float* __restrict__ W1) {  // [256,128] -> Bt[128][256]
    int t = blockIdx.x * blockDim.x + threadIdx.x;
    if (t >= 128 * INCH) return;
    int n = t / INCH, k = t % INCH;
    float w = W1[k * HIDC + n];
    __nv_bfloat16 h = __float2bfloat16_rn(w);
    g_bt1h[t] = h;
    g_bt1l[t] = __float2bfloat16_rn(w - __bfloat162float(h));
}
__global__ void k_prepB2(const float* __restrict__ Wmu, const float* __restrict__ Wls) {
    int t = blockIdx.x * blockDim.x + threadIdx.x;
    if (t >= 128 * HIDC) return;
    int n = t / HIDC, k = t % HIDC;
    float w = (n < 64) ? Wmu[k * 64 + n] : Wls[k * 64 + (n - 64)];
    __nv_bfloat16 h = __float2bfloat16_rn(w);
    g_bt2h[t] = h;
    g_bt2l[t] = __float2bfloat16_rn(w - __bfloat162float(h));
}

// ---------------- mma.sync helpers ----------------
__device__ __forceinline__ void ldmx4(uint32_t& r0, uint32_t& r1, uint32_t& r2, uint32_t& r3,
                                      uint32_t addr) {
    asm volatile("ldmatrix.sync.aligned.m8n8.x4.shared.b16 {%0,%1,%2,%3}, [%4];"
                 : "=r"(r0), "=r"(r1), "=r"(r2), "=r"(r3) : "r"(addr));
}
__device__ __forceinline__ void mma16816(float* d, const uint32_t* a, uint32_t b0, uint32_t b1) {
    asm volatile(
        "mma.sync.aligned.m16n8k16.row.col.f32.bf16.bf16.f32 "
        "{%0,%1,%2,%3}, {%4,%5,%6,%7}, {%8,%9}, {%0,%1,%2,%3};"
        : "+f"(d[0]), "+f"(d[1]), "+f"(d[2]), "+f"(d[3])
        : "r"(a[0]), "r"(a[1]), "r"(a[2]), "r"(a[3]), "r"(b0), "r"(b1));
}

// ---------------- bf16 tensor-core GEMM: C[M,128] = A[M,K] @ Bt^T ----------------
// block: 256 thr = 8 warps (4m x 2n). tile 128x128, BK=32. smem stride 40 elems (80B).
#define SSTR 40

template <int K>
__global__ void __launch_bounds__(256) k_gemm_mma(
    const float* __restrict__ A,
    const __nv_bfloat16* __restrict__ Bth, const __nv_bfloat16* __restrict__ Btl,
    int M, float* __restrict__ C)
{
    __shared__ __nv_bfloat16 Ash[128 * SSTR];
    __shared__ __nv_bfloat16 Asl[128 * SSTR];
    __shared__ __nv_bfloat16 Bsh[128 * SSTR];
    __shared__ __nv_bfloat16 Bsl[128 * SSTR];

    int tid = threadIdx.x, lane = tid & 31, wid = tid >> 5;
    int warp_m = wid & 3;   // 0..3 : rows warp_m*32
    int warp_n = wid >> 2;  // 0..1 : cols warp_n*64
    int row0 = blockIdx.x * 128;

    uint32_t uAh = smem_u32(Ash), uAl = smem_u32(Asl);
    uint32_t uBh = smem_u32(Bsh), uBl = smem_u32(Bsl);

    float acc[2][8][4];
#pragma unroll
    for (int mt = 0; mt < 2; mt++)
#pragma unroll
        for (int nt = 0; nt < 8; nt++)
#pragma unroll
            for (int q = 0; q < 4; q++) acc[mt][nt][q] = 0.f;

    for (int k0 = 0; k0 < K; k0 += 32) {
        // ---- load A 128x32 fp32, split hi/lo, store to smem (stride 40)
#pragma unroll
        for (int it = 0; it < 4; it++) {
            int id = it * 256 + tid;       // 0..1023 float4s
            int r = id >> 3;               // row 0..127
            int c4 = id & 7;               // float4 idx, cols c4*4..+3
            int grow = row0 + r;
            float4 v = make_float4(0.f, 0.f, 0.f, 0.f);
            if (grow < M) v = *(const float4*)(A + (size_t)grow * K + k0 + c4 * 4);
            __nv_bfloat162 h01 = __floats2bfloat162_rn(v.x, v.y);
            __nv_bfloat162 h23 = __floats2bfloat162_rn(v.z, v.w);
            float2 hf01 = __bfloat1622float2(h01);
            float2 hf23 = __bfloat1622float2(h23);
            __nv_bfloat162 l01 = __floats2bfloat162_rn(v.x - hf01.x, v.y - hf01.y);
            __nv_bfloat162 l23 = __floats2bfloat162_rn(v.z - hf23.x, v.w - hf23.y);
            uint32_t off = (uint32_t)(r * SSTR + c4 * 4) * 2;
            asm volatile("st.shared.v2.b32 [%0], {%1, %2};"
                         :: "r"(uAh + off), "r"(*(uint32_t*)&h01), "r"(*(uint32_t*)&h23) : "memory");
            asm volatile("st.shared.v2.b32 [%0], {%1, %2};"
                         :: "r"(uAl + off), "r"(*(uint32_t*)&l01), "r"(*(uint32_t*)&l23) : "memory");
        }
        // ---- load B 128x32 bf16 hi/lo (pre-split), store to smem
#pragma unroll
        for (int it = 0; it < 2; it++) {
            int id = it * 256 + tid;       // 0..511 uint4s
            int r = id >> 2;               // n row 0..127
            int c8 = id & 3;               // 8-elem unit
            uint4 vh = *(const uint4*)(Bth + (size_t)r * K + k0 + c8 * 8);
            uint4 vl = *(const uint4*)(Btl + (size_t)r * K + k0 + c8 * 8);
            uint32_t off = (uint32_t)(r * SSTR + c8 * 8) * 2;
            asm volatile("st.shared.v4.b32 [%0], {%1, %2, %3, %4};"
                         :: "r"(uBh + off), "r"(vh.x), "r"(vh.y), "r"(vh.z), "r"(vh.w) : "memory");
            asm volatile("st.shared.v4.b32 [%0], {%1, %2, %3, %4};"
                         :: "r"(uBl + off), "r"(vl.x), "r"(vl.y), "r"(vl.z), "r"(vl.w) : "memory");
        }
        __syncthreads();

#pragma unroll
        for (int ks = 0; ks < 32; ks += 16) {
            // A fragments, 2 m-tiles, hi+lo
            uint32_t Ah[2][4], Al[2][4];
            {
                int arow = warp_m * 32 + (lane & 15);
                int acol = ks + ((lane & 16) >> 1);
#pragma unroll
                for (int mt = 0; mt < 2; mt++) {
                    uint32_t aoff = (uint32_t)((arow + mt * 16) * SSTR + acol) * 2;
                    ldmx4(Ah[mt][0], Ah[mt][1], Ah[mt][2], Ah[mt][3], uAh + aoff);
                    ldmx4(Al[mt][0], Al[mt][1], Al[mt][2], Al[mt][3], uAl + aoff);
                }
            }
            // B: 4 chunks of 2 n8-tiles
            int brow_base = (lane & 7) + ((lane & 16) >> 1);
            int bcol = ks + (lane & 8);
#pragma unroll
            for (int nt2 = 0; nt2 < 4; nt2++) {
                int nbase = warp_n * 64 + nt2 * 16;
                uint32_t boff = (uint32_t)((nbase + brow_base) * SSTR + bcol) * 2;
                uint32_t bh0, bh1, bh2, bh3, bl0, bl1, bl2, bl3;
                ldmx4(bh0, bh1, bh2, bh3, uBh + boff);
                ldmx4(bl0, bl1, bl2, bl3, uBl + boff);
#pragma unroll
                for (int mt = 0; mt < 2; mt++) {
                    mma16816(acc[mt][nt2 * 2 + 0], Ah[mt], bh0, bh1);
                    mma16816(acc[mt][nt2 * 2 + 1], Ah[mt], bh2, bh3);
                    mma16816(acc[mt][nt2 * 2 + 0], Al[mt], bh0, bh1);
                    mma16816(acc[mt][nt2 * 2 + 1], Al[mt], bh2, bh3);
                    mma16816(acc[mt][nt2 * 2 + 0], Ah[mt], bl0, bl1);
                    mma16816(acc[mt][nt2 * 2 + 1], Ah[mt], bl2, bl3);
                }
            }
        }
        __syncthreads();
    }

    // ---- epilogue
#pragma unroll
    for (int mt = 0; mt < 2; mt++) {
        int r = row0 + warp_m * 32 + mt * 16 + (lane >> 2);
#pragma unroll
        for (int nt = 0; nt < 8; nt++) {
            int col = warp_n * 64 + nt * 8 + (lane & 3) * 2;
            if (r < M)
                *(float2*)(C + (size_t)r * HIDC + col) = make_float2(acc[mt][nt][0], acc[mt][nt][1]);
            if (r + 8 < M)
                *(float2*)(C + (size_t)(r + 8) * HIDC + col) = make_float2(acc[mt][nt][2], acc[mt][nt][3]);
        }
    }
}

// ---------------- aggregation: warp per node, float4 per lane ----------------
__global__ void __launch_bounds__(256) k_agg1(const float* __restrict__ b1) {
    int warp = (blockIdx.x * blockDim.x + threadIdx.x) >> 5;
    int lane = threadIdx.x & 31;
    if (warp >= NN) return;
    int v = warp;
    float dv = g_dinv[v];
    const float4* H = (const float4*)g_hpre;
    float4 self = H[(size_t)v * 32 + lane];
    float4 acc;
    acc.x = self.x * dv; acc.y = self.y * dv; acc.z = self.z * dv; acc.w = self.w * dv;
    int e1 = g_rowptr[v + 1];
    for (int e = g_rowptr[v]; e < e1; e++) {
        int s = g_csrc[e];
        float w = g_dinv[s];
        float4 hv = H[(size_t)s * 32 + lane];
        acc.x = fmaf(w, hv.x, acc.x);
        acc.y = fmaf(w, hv.y, acc.y);
        acc.z = fmaf(w, hv.z, acc.z);
        acc.w = fmaf(w, hv.w, acc.w);
    }
    float4 bb = ((const float4*)b1)[lane];
    float4 o;
    o.x = fmaxf(fmaf(acc.x, dv, bb.x), 0.f);
    o.y = fmaxf(fmaf(acc.y, dv, bb.y), 0.f);
    o.z = fmaxf(fmaf(acc.z, dv, bb.z), 0.f);
    o.w = fmaxf(fmaf(acc.w, dv, bb.w), 0.f);
    ((float4*)g_h)[(size_t)v * 32 + lane] = o;
}

__global__ void __launch_bounds__(256) k_agg2(
    const float* __restrict__ bmu, const float* __restrict__ bls,
    float* __restrict__ out)
{
    int warp = (blockIdx.x * blockDim.x + threadIdx.x) >> 5;
    int lane = threadIdx.x & 31;
    if (warp >= NN) return;
    int v = warp;
    float dv = g_dinv[v];
    const float4* G = (const float4*)g_g;
    float4 self = G[(size_t)v * 32 + lane];
    float4 acc;
    acc.x = self.x * dv; acc.y = self.y * dv; acc.z = self.z * dv; acc.w = self.w * dv;
    int e1 = g_rowptr[v + 1];
    for (int e = g_rowptr[v]; e < e1; e++) {
        int s = g_csrc[e];
        float w = g_dinv[s];
        float4 hv = G[(size_t)s * 32 + lane];
        acc.x = fmaf(w, hv.x, acc.x);
        acc.y = fmaf(w, hv.y, acc.y);
        acc.z = fmaf(w, hv.z, acc.z);
        acc.w = fmaf(w, hv.w, acc.w);
    }
    if (lane < 16) {
        float4 bb = ((const float4*)bmu)[lane];
        float4 o;
        o.x = fmaf(acc.x, dv, bb.x);
        o.y = fmaf(acc.y, dv, bb.y);
        o.z = fmaf(acc.z, dv, bb.z);
        o.w = fmaf(acc.w, dv, bb.w);
        ((float4*)out)[(size_t)v * 16 + lane] = o;
    } else {
        float4 bb = ((const float4*)bls)[lane - 16];
        float4 o;
        o.x = fmaf(acc.x, dv, bb.x);
        o.y = fmaf(acc.y, dv, bb.y);
        o.z = fmaf(acc.z, dv, bb.z);
        o.w = fmaf(acc.w, dv, bb.w);
        ((float4*)(out + (size_t)NN * OUTC))[(size_t)v * 16 + (lane - 16)] = o;
    }
}

// ---------------- launch ----------------
extern "C" void kernel_launch(void* const* d_in, const int* in_sizes, int n_in,
                              void* d_out, int out_size) {
    const float* x    = (const float*)d_in[0];
    const float* W1   = (const float*)d_in[1];
    const float* b1   = (const float*)d_in[2];
    const float* Wmu  = (const float*)d_in[3];
    const float* bmu  = (const float*)d_in[4];
    const float* Wls  = (const float*)d_in[5];
    const float* bls  = (const float*)d_in[6];
    const int*   ei   = (const int*)d_in[7];
    float* out = (float*)d_out;

    void *p_hpre = nullptr, *p_h = nullptr, *p_g = nullptr;
    void *p_b1h = nullptr, *p_b1l = nullptr, *p_b2h = nullptr, *p_b2l = nullptr;
    cudaGetSymbolAddress(&p_hpre, g_hpre);
    cudaGetSymbolAddress(&p_h, g_h);
    cudaGetSymbolAddress(&p_g, g_g);
    cudaGetSymbolAddress(&p_b1h, g_bt1h);
    cudaGetSymbolAddress(&p_b1l, g_bt1l);
    cudaGetSymbolAddress(&p_b2h, g_bt2h);
    cudaGetSymbolAddress(&p_b2l, g_bt2l);

    int nblk_n = (NN + 255) / 256;
    int nblk_e = (EE + 255) / 256;
    int nblk_s = (NN + 1023) / 1024;

    k_init_deg<<<nblk_n, 256>>>();
    k_count<<<nblk_e, 256>>>(ei);
    k_dinv<<<nblk_n, 256>>>();
    k_scan1<<<nblk_s, 1024>>>();
    k_scan2<<<1, 128>>>();
    k_scan3<<<nblk_s, 1024>>>();
    k_fill<<<nblk_e, 256>>>(ei);
    k_prepB1<<<(128 * INCH + 255) / 256, 256>>>(W1);
    k_prepB2<<<(128 * HIDC + 255) / 256, 256>>>(Wmu, Wls);

    int gblk = (NN + 127) / 128;  // 782
    k_gemm_mma<INCH><<<gblk, 256>>>(
        x, (const __nv_bfloat16*)p_b1h, (const __nv_bfloat16*)p_b1l, NN, (float*)p_hpre);
    k_agg1<<<(NN * 32 + 255) / 256, 256>>>(b1);
    k_gemm_mma<HIDC><<<gblk, 256>>>(
        (const float*)p_h, (const __nv_bfloat16*)p_b2h, (const __nv_bfloat16*)p_b2l, NN, (float*)p_g);
    k_agg2<<<(NN * 32 + 255) / 256, 256>>>(bmu, bls, out);
}